// round 4
// baseline (speedup 1.0000x reference)
#include <cuda_runtime.h>
#include <cuda_bf16.h>

#define N_NODES 30000
#define N_EDGES 480000
#define D 128
#define EPSF 1e-7f

// ---------------- scratch (device globals; no allocation allowed) ----------------
__device__ float g_hA[N_NODES * D];
__device__ float g_hB[N_NODES * D];
__device__ float g_m  [N_NODES * D];   // per-(node,channel) running max (softmax)
__device__ float g_den[N_NODES * D];   // sum exp
__device__ float g_num[N_NODES * D];   // sum exp*msg

// ---------------- no-return reduction helpers ------------------------------------
__device__ __forceinline__ void red_add_v4(float* addr, float a, float b, float c, float d) {
    asm volatile("red.global.add.v4.f32 [%0], {%1,%2,%3,%4};"
                 :: "l"(addr), "f"(a), "f"(b), "f"(c), "f"(d) : "memory");
}
__device__ __forceinline__ void red_max_s32(int* addr, int v) {
    asm volatile("red.global.max.s32 [%0], %1;" :: "l"(addr), "r"(v) : "memory");
}

// ---------------- zero the softmax scratch (bit-zero == 0.0f) -------------------
__global__ void __launch_bounds__(256) zero_scratch() {
    int i = blockIdx.x * 256 + threadIdx.x;          // 960000 float4 per array
    float4 z = make_float4(0.f, 0.f, 0.f, 0.f);
    ((float4*)g_m)[i]   = z;
    ((float4*)g_den)[i] = z;
    ((float4*)g_num)[i] = z;
}

// ---------------- shared GEMM tail: out[nb..nb+31][:] = sIn @ W + bias ----------
__device__ __forceinline__ void gemm128_tail(
    float (*sIn)[128], float (*sW)[128],
    const float* __restrict__ W, const float* __restrict__ bias,
    float* __restrict__ out, int nb, int t)
{
    float acc[32];
    #pragma unroll
    for (int n = 0; n < 32; n++) acc[n] = 0.f;

    for (int k0 = 0; k0 < 128; k0 += 64) {
        __syncthreads();
        // cooperative load of 64x128 W tile (8192 floats, 128 threads -> 16 float4 each)
        const float4* Wsrc = (const float4*)(W + k0 * 128);
        float4*       Wdst = (float4*)&sW[0][0];
        #pragma unroll
        for (int i = 0; i < 16; i++) Wdst[t + i * 128] = Wsrc[t + i * 128];
        __syncthreads();

        for (int k = 0; k < 64; k += 4) {
            float w0 = sW[k + 0][t];
            float w1 = sW[k + 1][t];
            float w2 = sW[k + 2][t];
            float w3 = sW[k + 3][t];
            #pragma unroll
            for (int n = 0; n < 32; n++) {
                float4 a = *(const float4*)&sIn[n][k0 + k];   // broadcast across lanes
                acc[n] = fmaf(a.x, w0, acc[n]);
                acc[n] = fmaf(a.y, w1, acc[n]);
                acc[n] = fmaf(a.z, w2, acc[n]);
                acc[n] = fmaf(a.w, w3, acc[n]);
            }
        }
    }
    float b = bias[t];
    #pragma unroll
    for (int n = 0; n < 32; n++) {
        int node = nb + n;
        if (node < N_NODES) out[node * D + t] = acc[n] + b;
    }
}

// ---------------- node encoder: h0 = relu(x@Wn1+bn1)@Wn2+bn2 -> g_hA ------------
__global__ void __launch_bounds__(128) node_encoder(
    const float* __restrict__ x,
    const float* __restrict__ Wn1, const float* __restrict__ bn1,
    const float* __restrict__ Wn2, const float* __restrict__ bn2)
{
    __shared__ float sIn[32][128];
    __shared__ float sW [64][128];
    int nb = blockIdx.x * 32;
    int t  = threadIdx.x;

    float w[7];
    #pragma unroll
    for (int j = 0; j < 7; j++) w[j] = Wn1[j * D + t];
    float b1 = bn1[t];

    for (int n = 0; n < 32; n++) {
        int node = nb + n;
        float v = 0.f;
        if (node < N_NODES) {
            float s = b1;
            #pragma unroll
            for (int j = 0; j < 7; j++) s = fmaf(x[node * 7 + j], w[j], s);
            v = fmaxf(s, 0.f);
        }
        sIn[n][t] = v;
    }
    gemm128_tail(sIn, sW, Wn2, bn2, g_hA, nb, t);
}

// ---------------- per-edge scalar fetch with warp broadcast ----------------------
// 16 lanes per edge; only the group leader loads, then shuffles to the group.
__device__ __forceinline__ void load_edge_scalars(
    const int* __restrict__ ei, const float* __restrict__ ea,
    int e, int lane, int& s, int& d, float& a)
{
    int leader = lane & ~15;                 // lane 0 or 16 within the warp
    int sv = 0, dv = 0; float av = 0.f;
    if (lane == leader) {
        sv = ei[e];
        dv = ei[N_EDGES + e];
        av = ea[e];
    }
    s = __shfl_sync(0xffffffffu, sv, leader);
    d = __shfl_sync(0xffffffffu, dv, leader);
    a = __shfl_sync(0xffffffffu, av, leader);
}

// ---------------- edge pass 1: per-(dst,channel) max of msg ---------------------
// msg = relu(h[src] + ea*We + be) + EPS  (>0, so s32 red-max on float bits works)
// 8 channels per thread; 16 threads per edge. Grid exactly covers N_EDGES*16.
__global__ void __launch_bounds__(256) edge_pass1(
    int hsel, const int* __restrict__ ei, const float* __restrict__ ea,
    const float* __restrict__ We, const float* __restrict__ be)
{
    const float* __restrict__ h = hsel ? g_hB : g_hA;
    int tid  = blockIdx.x * 256 + threadIdx.x;
    int e    = tid >> 4;
    int lane = threadIdx.x & 31;
    int q    = (tid & 15) << 3;

    int s, d; float a;
    load_edge_scalars(ei, ea, e, lane, s, d, a);

    float4 h0 = *(const float4*)(h  + s * D + q);
    float4 h1 = *(const float4*)(h  + s * D + q + 4);
    float4 w0 = *(const float4*)(We + q);
    float4 w1 = *(const float4*)(We + q + 4);
    float4 b0 = *(const float4*)(be + q);
    float4 b1 = *(const float4*)(be + q + 4);

    float m0 = fmaxf(fmaf(a, w0.x, h0.x + b0.x), 0.f) + EPSF;
    float m1 = fmaxf(fmaf(a, w0.y, h0.y + b0.y), 0.f) + EPSF;
    float m2 = fmaxf(fmaf(a, w0.z, h0.z + b0.z), 0.f) + EPSF;
    float m3 = fmaxf(fmaf(a, w0.w, h0.w + b0.w), 0.f) + EPSF;
    float m4 = fmaxf(fmaf(a, w1.x, h1.x + b1.x), 0.f) + EPSF;
    float m5 = fmaxf(fmaf(a, w1.y, h1.y + b1.y), 0.f) + EPSF;
    float m6 = fmaxf(fmaf(a, w1.z, h1.z + b1.z), 0.f) + EPSF;
    float m7 = fmaxf(fmaf(a, w1.w, h1.w + b1.w), 0.f) + EPSF;

    int* mp = (int*)(g_m + d * D + q);
    red_max_s32(mp + 0, __float_as_int(m0));
    red_max_s32(mp + 1, __float_as_int(m1));
    red_max_s32(mp + 2, __float_as_int(m2));
    red_max_s32(mp + 3, __float_as_int(m3));
    red_max_s32(mp + 4, __float_as_int(m4));
    red_max_s32(mp + 5, __float_as_int(m5));
    red_max_s32(mp + 6, __float_as_int(m6));
    red_max_s32(mp + 7, __float_as_int(m7));
}

// ---------------- edge pass 2: accumulate sum(exp) and sum(exp*msg) -------------
__global__ void __launch_bounds__(256) edge_pass2(
    int hsel, const int* __restrict__ ei, const float* __restrict__ ea,
    const float* __restrict__ We, const float* __restrict__ be)
{
    const float* __restrict__ h = hsel ? g_hB : g_hA;
    int tid  = blockIdx.x * 256 + threadIdx.x;
    int e    = tid >> 4;
    int lane = threadIdx.x & 31;
    int q    = (tid & 15) << 3;

    int s, d; float a;
    load_edge_scalars(ei, ea, e, lane, s, d, a);

    float4 h0 = *(const float4*)(h  + s * D + q);
    float4 h1 = *(const float4*)(h  + s * D + q + 4);
    float4 w0 = *(const float4*)(We + q);
    float4 w1 = *(const float4*)(We + q + 4);
    float4 b0 = *(const float4*)(be + q);
    float4 b1 = *(const float4*)(be + q + 4);

    float m0 = fmaxf(fmaf(a, w0.x, h0.x + b0.x), 0.f) + EPSF;
    float m1 = fmaxf(fmaf(a, w0.y, h0.y + b0.y), 0.f) + EPSF;
    float m2 = fmaxf(fmaf(a, w0.z, h0.z + b0.z), 0.f) + EPSF;
    float m3 = fmaxf(fmaf(a, w0.w, h0.w + b0.w), 0.f) + EPSF;
    float m4 = fmaxf(fmaf(a, w1.x, h1.x + b1.x), 0.f) + EPSF;
    float m5 = fmaxf(fmaf(a, w1.y, h1.y + b1.y), 0.f) + EPSF;
    float m6 = fmaxf(fmaf(a, w1.z, h1.z + b1.z), 0.f) + EPSF;
    float m7 = fmaxf(fmaf(a, w1.w, h1.w + b1.w), 0.f) + EPSF;

    float4 x0 = *(const float4*)(g_m + d * D + q);
    float4 x1 = *(const float4*)(g_m + d * D + q + 4);
    float e0 = __expf(m0 - x0.x);
    float e1 = __expf(m1 - x0.y);
    float e2 = __expf(m2 - x0.z);
    float e3 = __expf(m3 - x0.w);
    float e4 = __expf(m4 - x1.x);
    float e5 = __expf(m5 - x1.y);
    float e6 = __expf(m6 - x1.z);
    float e7 = __expf(m7 - x1.w);

    float* den = g_den + d * D + q;
    float* num = g_num + d * D + q;
    red_add_v4(den,     e0, e1, e2, e3);
    red_add_v4(den + 4, e4, e5, e6, e7);
    red_add_v4(num,     e0 * m0, e1 * m1, e2 * m2, e3 * m3);
    red_add_v4(num + 4, e4 * m4, e5 * m5, e6 * m6, e7 * m7);
}

// ---------------- node update: h_out = (num/den + h_in) @ Wg + bg ---------------
// Also resets the softmax scratch to zero for the next layer (and next replay).
__global__ void __launch_bounds__(128) node_update(
    int hsel, const float* __restrict__ Wg_l, const float* __restrict__ bg_l)
{
    const float* __restrict__ h_in = hsel ? g_hB : g_hA;
    float*                    h_out = hsel ? g_hA : g_hB;

    __shared__ float sIn[32][128];
    __shared__ float sW [64][128];
    int nb = blockIdx.x * 32;
    int t  = threadIdx.x;

    for (int n = 0; n < 32; n++) {
        int node = nb + n;
        float v = 0.f;
        if (node < N_NODES) {
            int   idx = node * D + t;
            float den = g_den[idx];
            float agg = (den > 0.f) ? (g_num[idx] / den) : 0.f;
            v = agg + h_in[idx];
            // reset scratch for the next layer / next graph replay
            g_den[idx] = 0.f;
            g_num[idx] = 0.f;
            g_m[idx]   = 0.f;
        }
        sIn[n][t] = v;
    }
    gemm128_tail(sIn, sW, Wg_l, bg_l, h_out, nb, t);
}

// ---------------- output head: out = h @ Wo + bo  (warp per node) ---------------
__global__ void __launch_bounds__(256) head_kernel(
    const float* __restrict__ Wo, const float* __restrict__ bo,
    float* __restrict__ out)
{
    int warp = (blockIdx.x * 256 + threadIdx.x) >> 5;
    int lane = threadIdx.x & 31;
    if (warp >= N_NODES) return;
    const float* row = g_hA + warp * D;   // after 4 layers h lives in g_hA

    float a0 = 0.f, a1 = 0.f, a2 = 0.f;
    #pragma unroll
    for (int k = lane; k < D; k += 32) {
        float v = row[k];
        a0 = fmaf(v, Wo[k * 3 + 0], a0);
        a1 = fmaf(v, Wo[k * 3 + 1], a1);
        a2 = fmaf(v, Wo[k * 3 + 2], a2);
    }
    #pragma unroll
    for (int off = 16; off; off >>= 1) {
        a0 += __shfl_down_sync(0xffffffffu, a0, off);
        a1 += __shfl_down_sync(0xffffffffu, a1, off);
        a2 += __shfl_down_sync(0xffffffffu, a2, off);
    }
    if (lane == 0) {
        out[warp * 3 + 0] = a0 + bo[0];
        out[warp * 3 + 1] = a1 + bo[1];
        out[warp * 3 + 2] = a2 + bo[2];
    }
}

// ---------------- launch --------------------------------------------------------
extern "C" void kernel_launch(void* const* d_in, const int* in_sizes, int n_in,
                              void* d_out, int out_size)
{
    const float* x   = (const float*)d_in[0];
    const int*   ei  = (const int*)  d_in[1];
    const float* ea  = (const float*)d_in[2];
    const float* Wn1 = (const float*)d_in[3];
    const float* bn1 = (const float*)d_in[4];
    const float* Wn2 = (const float*)d_in[5];
    const float* bn2 = (const float*)d_in[6];
    const float* We  = (const float*)d_in[7];
    const float* be  = (const float*)d_in[8];
    const float* Wg  = (const float*)d_in[9];
    const float* bg  = (const float*)d_in[10];
    const float* Wo  = (const float*)d_in[11];
    const float* bo  = (const float*)d_in[12];
    float* out = (float*)d_out;

    const int NODE_BLOCKS = (N_NODES + 31) / 32;          // 938
    const int EDGE_BLOCKS = (N_EDGES * 16) / 256;         // 30000 (exact)
    const int ZERO_BLOCKS = (N_NODES * D / 4) / 256;      // 3750 (exact)

    // one upfront zero (insurance; node_update keeps the invariant thereafter)
    zero_scratch<<<ZERO_BLOCKS, 256>>>();
    node_encoder<<<NODE_BLOCKS, 128>>>(x, Wn1, bn1, Wn2, bn2);

    for (int l = 0; l < 4; l++) {
        int hsel = l & 1;   // 0: h in g_hA, 1: h in g_hB
        edge_pass1<<<EDGE_BLOCKS, 256>>>(hsel, ei, ea, We, be);
        edge_pass2<<<EDGE_BLOCKS, 256>>>(hsel, ei, ea, We, be);
        node_update<<<NODE_BLOCKS, 128>>>(hsel, Wg + (size_t)l * D * D, bg + (size_t)l * D);
    }

    head_kernel<<<(N_NODES * 32 + 255) / 256, 256>>>(Wo, bo, out);
}

// round 11
// speedup vs baseline: 3.8379x; 3.8379x over previous
#include <cuda_runtime.h>
#include <cuda_bf16.h>

#define N_NODES 30000
#define N_EDGES 480000
#define D 128
#define EPSF 1e-7f

// ---------------- scratch (device globals; no allocation allowed) ----------------
__device__ float g_hA [N_NODES * D];
__device__ float g_hB [N_NODES * D];
__device__ float g_pre[N_NODES * D];      // (agg + h) per layer, GEMM input

// CSR build scratch
__device__ int  g_cnt[N_NODES];
__device__ int  g_cur[N_NODES];
__device__ int  g_row[N_NODES + 1];
__device__ int2 g_edge[N_EDGES];          // {src, float_bits(edge_attr)}

// ---------------- CSR build ------------------------------------------------------
__global__ void __launch_bounds__(256) csr_zero() {
    int i = blockIdx.x * 256 + threadIdx.x;
    if (i < N_NODES) { g_cnt[i] = 0; g_cur[i] = 0; }
}

__global__ void __launch_bounds__(256) csr_hist(const int* __restrict__ ei) {
    int e = blockIdx.x * 256 + threadIdx.x;
    if (e < N_EDGES) atomicAdd(&g_cnt[ei[N_EDGES + e]], 1);
}

// single-block exclusive scan of g_cnt -> g_row (30000 elems, 1024 threads x 30)
__global__ void __launch_bounds__(1024) csr_scan() {
    __shared__ int part[1024];
    const int t = threadIdx.x;
    const int CH = 30;                       // 1024*30 = 30720 >= 30000
    int base = t * CH;
    int local[CH];
    int sum = 0;
    #pragma unroll
    for (int i = 0; i < CH; i++) {
        int idx = base + i;
        int v = (idx < N_NODES) ? g_cnt[idx] : 0;
        local[i] = sum;                      // exclusive within chunk
        sum += v;
    }
    part[t] = sum;
    __syncthreads();
    // Hillis–Steele inclusive scan over partials (read, sync, write, sync)
    for (int off = 1; off < 1024; off <<= 1) {
        int v = (t >= off) ? part[t - off] : 0;
        __syncthreads();
        part[t] += v;
        __syncthreads();
    }
    int exoff = part[t] - sum;               // exclusive offset for this chunk
    #pragma unroll
    for (int i = 0; i < CH; i++) {
        int idx = base + i;
        if (idx < N_NODES) g_row[idx] = exoff + local[i];
    }
    if (t == 1023) g_row[N_NODES] = part[1023];   // = N_EDGES
}

__global__ void __launch_bounds__(256) csr_scatter(
    const int* __restrict__ ei, const float* __restrict__ ea)
{
    int e = blockIdx.x * 256 + threadIdx.x;
    if (e >= N_EDGES) return;
    int s = ei[e];
    int d = ei[N_EDGES + e];
    int pos = g_row[d] + atomicAdd(&g_cur[d], 1);
    g_edge[pos] = make_int2(s, __float_as_int(ea[e]));
}

// ---------------- shared GEMM tail: out[nb..nb+31][:] = sIn @ W + bias ----------
__device__ __forceinline__ void gemm128_tail(
    float (*sIn)[128], float (*sW)[128],
    const float* __restrict__ W, const float* __restrict__ bias,
    float* __restrict__ out, int nb, int t)
{
    float acc[32];
    #pragma unroll
    for (int n = 0; n < 32; n++) acc[n] = 0.f;

    for (int k0 = 0; k0 < 128; k0 += 64) {
        __syncthreads();
        const float4* Wsrc = (const float4*)(W + k0 * 128);
        float4*       Wdst = (float4*)&sW[0][0];
        #pragma unroll
        for (int i = 0; i < 16; i++) Wdst[t + i * 128] = Wsrc[t + i * 128];
        __syncthreads();

        for (int k = 0; k < 64; k += 4) {
            float w0 = sW[k + 0][t];
            float w1 = sW[k + 1][t];
            float w2 = sW[k + 2][t];
            float w3 = sW[k + 3][t];
            #pragma unroll
            for (int n = 0; n < 32; n++) {
                float4 a = *(const float4*)&sIn[n][k0 + k];   // broadcast
                acc[n] = fmaf(a.x, w0, acc[n]);
                acc[n] = fmaf(a.y, w1, acc[n]);
                acc[n] = fmaf(a.z, w2, acc[n]);
                acc[n] = fmaf(a.w, w3, acc[n]);
            }
        }
    }
    float b = bias[t];
    #pragma unroll
    for (int n = 0; n < 32; n++) {
        int node = nb + n;
        if (node < N_NODES) out[node * D + t] = acc[n] + b;
    }
}

// ---------------- node encoder: h0 = relu(x@Wn1+bn1)@Wn2+bn2 -> g_hA ------------
__global__ void __launch_bounds__(128) node_encoder(
    const float* __restrict__ x,
    const float* __restrict__ Wn1, const float* __restrict__ bn1,
    const float* __restrict__ Wn2, const float* __restrict__ bn2)
{
    __shared__ float sIn[32][128];
    __shared__ float sW [64][128];
    int nb = blockIdx.x * 32;
    int t  = threadIdx.x;

    float w[7];
    #pragma unroll
    for (int j = 0; j < 7; j++) w[j] = Wn1[j * D + t];
    float b1 = bn1[t];

    for (int n = 0; n < 32; n++) {
        int node = nb + n;
        float v = 0.f;
        if (node < N_NODES) {
            float s = b1;
            #pragma unroll
            for (int j = 0; j < 7; j++) s = fmaf(x[node * 7 + j], w[j], s);
            v = fmaxf(s, 0.f);
        }
        sIn[n][t] = v;
    }
    gemm128_tail(sIn, sW, Wn2, bn2, g_hA, nb, t);
}

// ---------------- gather + online segment softmax (warp per dst node) -----------
// Each lane owns 4 channels. Two-stage software pipeline: while processing edge
// k's softmax math, edge k+1's (src,a) and h-row loads are already in flight.
__global__ void __launch_bounds__(256) genconv_gather(
    int hsel, const float* __restrict__ We, const float* __restrict__ be)
{
    const float* __restrict__ h = hsel ? g_hB : g_hA;
    int node = blockIdx.x * 8 + (threadIdx.x >> 5);
    if (node >= N_NODES) return;
    int lane = threadIdx.x & 31;
    int q    = lane << 2;

    int beg = g_row[node];
    int end = g_row[node + 1];

    float4 wv = *(const float4*)(We + q);
    float4 bv = *(const float4*)(be + q);

    float m0 = -1e30f, m1 = -1e30f, m2 = -1e30f, m3 = -1e30f;
    float d0 = 0.f, d1 = 0.f, d2 = 0.f, d3 = 0.f;
    float n0 = 0.f, n1 = 0.f, n2 = 0.f, n3 = 0.f;

    if (beg < end) {
        // stage 0: issue first edge's loads
        int2   epk = g_edge[beg];
        float4 hv  = *(const float4*)(h + epk.x * D + q);
        float  a   = __int_as_float(epk.y);

        for (int k = beg + 1; k < end; k++) {
            // issue next edge's loads before touching this edge's data
            int2   epk_n = g_edge[k];
            float4 hv_n  = *(const float4*)(h + epk_n.x * D + q);
            float  a_n   = __int_as_float(epk_n.y);

            float msg0 = fmaxf(fmaf(a, wv.x, hv.x + bv.x), 0.f) + EPSF;
            float msg1 = fmaxf(fmaf(a, wv.y, hv.y + bv.y), 0.f) + EPSF;
            float msg2 = fmaxf(fmaf(a, wv.z, hv.z + bv.z), 0.f) + EPSF;
            float msg3 = fmaxf(fmaf(a, wv.w, hv.w + bv.w), 0.f) + EPSF;

            if (msg0 > m0) { float r = __expf(m0 - msg0); d0 = fmaf(d0, r, 1.f); n0 = fmaf(n0, r, msg0); m0 = msg0; }
            else           { float t = __expf(msg0 - m0); d0 += t;               n0 = fmaf(t, msg0, n0); }
            if (msg1 > m1) { float r = __expf(m1 - msg1); d1 = fmaf(d1, r, 1.f); n1 = fmaf(n1, r, msg1); m1 = msg1; }
            else           { float t = __expf(msg1 - m1); d1 += t;               n1 = fmaf(t, msg1, n1); }
            if (msg2 > m2) { float r = __expf(m2 - msg2); d2 = fmaf(d2, r, 1.f); n2 = fmaf(n2, r, msg2); m2 = msg2; }
            else           { float t = __expf(msg2 - m2); d2 += t;               n2 = fmaf(t, msg2, n2); }
            if (msg3 > m3) { float r = __expf(m3 - msg3); d3 = fmaf(d3, r, 1.f); n3 = fmaf(n3, r, msg3); m3 = msg3; }
            else           { float t = __expf(msg3 - m3); d3 += t;               n3 = fmaf(t, msg3, n3); }

            hv = hv_n; a = a_n;
        }
        // drain last edge
        float msg0 = fmaxf(fmaf(a, wv.x, hv.x + bv.x), 0.f) + EPSF;
        float msg1 = fmaxf(fmaf(a, wv.y, hv.y + bv.y), 0.f) + EPSF;
        float msg2 = fmaxf(fmaf(a, wv.z, hv.z + bv.z), 0.f) + EPSF;
        float msg3 = fmaxf(fmaf(a, wv.w, hv.w + bv.w), 0.f) + EPSF;

        if (msg0 > m0) { float r = __expf(m0 - msg0); d0 = fmaf(d0, r, 1.f); n0 = fmaf(n0, r, msg0); m0 = msg0; }
        else           { float t = __expf(msg0 - m0); d0 += t;               n0 = fmaf(t, msg0, n0); }
        if (msg1 > m1) { float r = __expf(m1 - msg1); d1 = fmaf(d1, r, 1.f); n1 = fmaf(n1, r, msg1); m1 = msg1; }
        else           { float t = __expf(msg1 - m1); d1 += t;               n1 = fmaf(t, msg1, n1); }
        if (msg2 > m2) { float r = __expf(m2 - msg2); d2 = fmaf(d2, r, 1.f); n2 = fmaf(n2, r, msg2); m2 = msg2; }
        else           { float t = __expf(msg2 - m2); d2 += t;               n2 = fmaf(t, msg2, n2); }
        if (msg3 > m3) { float r = __expf(m3 - msg3); d3 = fmaf(d3, r, 1.f); n3 = fmaf(n3, r, msg3); m3 = msg3; }
        else           { float t = __expf(msg3 - m3); d3 += t;               n3 = fmaf(t, msg3, n3); }
    }

    float4 hn = *(const float4*)(h + node * D + q);
    float4 o;
    o.x = (d0 > 0.f ? n0 / d0 : 0.f) + hn.x;
    o.y = (d1 > 0.f ? n1 / d1 : 0.f) + hn.y;
    o.z = (d2 > 0.f ? n2 / d2 : 0.f) + hn.z;
    o.w = (d3 > 0.f ? n3 / d3 : 0.f) + hn.w;
    *(float4*)(g_pre + node * D + q) = o;
}

// ---------------- node update: h_out = g_pre @ Wg + bg --------------------------
__global__ void __launch_bounds__(128) node_update(
    int hsel, const float* __restrict__ Wg_l, const float* __restrict__ bg_l)
{
    float* h_out = hsel ? g_hA : g_hB;

    __shared__ float sIn[32][128];
    __shared__ float sW [64][128];
    int nb = blockIdx.x * 32;
    int t  = threadIdx.x;

    for (int n = 0; n < 32; n++) {
        int node = nb + n;
        sIn[n][t] = (node < N_NODES) ? g_pre[node * D + t] : 0.f;
    }
    gemm128_tail(sIn, sW, Wg_l, bg_l, h_out, nb, t);
}

// ---------------- output head: out = h @ Wo + bo  (warp per node) ---------------
__global__ void __launch_bounds__(256) head_kernel(
    const float* __restrict__ Wo, const float* __restrict__ bo,
    float* __restrict__ out)
{
    int warp = (blockIdx.x * 256 + threadIdx.x) >> 5;
    int lane = threadIdx.x & 31;
    if (warp >= N_NODES) return;
    const float* row = g_hA + warp * D;   // after 4 layers h lives in g_hA

    float a0 = 0.f, a1 = 0.f, a2 = 0.f;
    #pragma unroll
    for (int k = lane; k < D; k += 32) {
        float v = row[k];
        a0 = fmaf(v, Wo[k * 3 + 0], a0);
        a1 = fmaf(v, Wo[k * 3 + 1], a1);
        a2 = fmaf(v, Wo[k * 3 + 2], a2);
    }
    #pragma unroll
    for (int off = 16; off; off >>= 1) {
        a0 += __shfl_down_sync(0xffffffffu, a0, off);
        a1 += __shfl_down_sync(0xffffffffu, a1, off);
        a2 += __shfl_down_sync(0xffffffffu, a2, off);
    }
    if (lane == 0) {
        out[warp * 3 + 0] = a0 + bo[0];
        out[warp * 3 + 1] = a1 + bo[1];
        out[warp * 3 + 2] = a2 + bo[2];
    }
}

// ---------------- launch --------------------------------------------------------
extern "C" void kernel_launch(void* const* d_in, const int* in_sizes, int n_in,
                              void* d_out, int out_size)
{
    const float* x   = (const float*)d_in[0];
    const int*   ei  = (const int*)  d_in[1];
    const float* ea  = (const float*)d_in[2];
    const float* Wn1 = (const float*)d_in[3];
    const float* bn1 = (const float*)d_in[4];
    const float* Wn2 = (const float*)d_in[5];
    const float* bn2 = (const float*)d_in[6];
    const float* We  = (const float*)d_in[7];
    const float* be  = (const float*)d_in[8];
    const float* Wg  = (const float*)d_in[9];
    const float* bg  = (const float*)d_in[10];
    const float* Wo  = (const float*)d_in[11];
    const float* bo  = (const float*)d_in[12];
    float* out = (float*)d_out;

    const int NODE_BLOCKS   = (N_NODES + 31) / 32;        // 938
    const int EDGE_BLOCKS   = (N_EDGES + 255) / 256;      // 1875
    const int CNT_BLOCKS    = (N_NODES + 255) / 256;      // 118
    const int GATHER_BLOCKS = (N_NODES + 7) / 8;          // 3750 (8 warps/block)

    // CSR build (graph constant; recomputed every call for determinism)
    csr_zero   <<<CNT_BLOCKS, 256>>>();
    csr_hist   <<<EDGE_BLOCKS, 256>>>(ei);
    csr_scan   <<<1, 1024>>>();
    csr_scatter<<<EDGE_BLOCKS, 256>>>(ei, ea);

    node_encoder<<<NODE_BLOCKS, 128>>>(x, Wn1, bn1, Wn2, bn2);

    for (int l = 0; l < 4; l++) {
        int hsel = l & 1;   // 0: h in g_hA, 1: h in g_hB
        genconv_gather<<<GATHER_BLOCKS, 256>>>(hsel, We, be);
        node_update   <<<NODE_BLOCKS, 128>>>(hsel, Wg + (size_t)l * D * D, bg + (size_t)l * D);
    }

    head_kernel<<<(N_NODES * 32 + 255) / 256, 256>>>(Wo, bo, out);
}

// round 12
// speedup vs baseline: 4.2643x; 1.1111x over previous
#include <cuda_runtime.h>
#include <cuda_bf16.h>

#define N_NODES 30000
#define N_EDGES 480000
#define D 128
#define EPSF 1e-7f
#define SIN_STRIDE 34   // 34 floats: 8B-aligned rows (136B) for direct LDS.64 pairs

// ---------------- scratch (device globals; no allocation allowed) ----------------
__device__ float g_hA [N_NODES * D];
__device__ float g_hB [N_NODES * D];
__device__ float g_pre[N_NODES * D];      // (agg + h) per layer, GEMM input

// CSR build scratch
__device__ int  g_cnt[N_NODES];
__device__ int  g_cur[N_NODES];
__device__ int  g_row[N_NODES + 1];
__device__ int2 g_edge[N_EDGES];          // {src, float_bits(edge_attr)}

// ---------------- packed f32x2 helpers ------------------------------------------
__device__ __forceinline__ unsigned long long ffma2(
    unsigned long long a, unsigned long long b, unsigned long long c)
{
    unsigned long long d;
    asm("fma.rn.f32x2 %0, %1, %2, %3;" : "=l"(d) : "l"(a), "l"(b), "l"(c));
    return d;
}
__device__ __forceinline__ unsigned long long pack2(float lo, float hi) {
    unsigned long long p;
    asm("mov.b64 %0, {%1, %2};" : "=l"(p) : "r"(__float_as_uint(lo)), "r"(__float_as_uint(hi)));
    return p;
}
__device__ __forceinline__ void unpack2(unsigned long long p, float& lo, float& hi) {
    unsigned int l, h;
    asm("mov.b64 {%0, %1}, %2;" : "=r"(l), "=r"(h) : "l"(p));
    lo = __uint_as_float(l); hi = __uint_as_float(h);
}

// ---------------- CSR build ------------------------------------------------------
__global__ void __launch_bounds__(256) csr_zero() {
    int i = blockIdx.x * 256 + threadIdx.x;
    if (i < N_NODES) { g_cnt[i] = 0; g_cur[i] = 0; }
}

__global__ void __launch_bounds__(256) csr_hist(const int* __restrict__ ei) {
    int e = blockIdx.x * 256 + threadIdx.x;
    if (e < N_EDGES) atomicAdd(&g_cnt[ei[N_EDGES + e]], 1);
}

// single-block exclusive scan of g_cnt -> g_row (30000 elems, 1024 threads x 30)
__global__ void __launch_bounds__(1024) csr_scan() {
    __shared__ int part[1024];
    const int t = threadIdx.x;
    const int CH = 30;
    int base = t * CH;
    int local[CH];
    int sum = 0;
    #pragma unroll
    for (int i = 0; i < CH; i++) {
        int idx = base + i;
        int v = (idx < N_NODES) ? g_cnt[idx] : 0;
        local[i] = sum;
        sum += v;
    }
    part[t] = sum;
    __syncthreads();
    for (int off = 1; off < 1024; off <<= 1) {
        int v = (t >= off) ? part[t - off] : 0;
        __syncthreads();
        part[t] += v;
        __syncthreads();
    }
    int exoff = part[t] - sum;
    #pragma unroll
    for (int i = 0; i < CH; i++) {
        int idx = base + i;
        if (idx < N_NODES) g_row[idx] = exoff + local[i];
    }
    if (t == 1023) g_row[N_NODES] = part[1023];
}

__global__ void __launch_bounds__(256) csr_scatter(
    const int* __restrict__ ei, const float* __restrict__ ea)
{
    int e = blockIdx.x * 256 + threadIdx.x;
    if (e >= N_EDGES) return;
    int s = ei[e];
    int d = ei[N_EDGES + e];
    int pos = g_row[d] + atomicAdd(&g_cur[d], 1);
    g_edge[pos] = make_int2(s, __float_as_int(ea[e]));
}

// ---------------- packed GEMM tail: out[nb..nb+31][:] = sInT^T @ W + bias -------
// sInT[k][n]: k = input channel (0..127), n = node within block (0..31).
// Node pairs (2j, 2j+1) read as one 64-bit word; fma.rn.f32x2 halves FFMA count.
__device__ __forceinline__ void gemm128_tail_T(
    float (*sInT)[SIN_STRIDE], float (*sW)[128],
    const float* __restrict__ W, const float* __restrict__ bias,
    float* __restrict__ out, int nb, int t)
{
    unsigned long long accp[16];
    #pragma unroll
    for (int j = 0; j < 16; j++) accp[j] = 0ull;   // bit-zero == {0.f, 0.f}

    for (int k0 = 0; k0 < 128; k0 += 64) {
        __syncthreads();
        const float4* Wsrc = (const float4*)(W + k0 * 128);
        float4*       Wdst = (float4*)&sW[0][0];
        #pragma unroll
        for (int i = 0; i < 16; i++) Wdst[t + i * 128] = Wsrc[t + i * 128];
        __syncthreads();

        #pragma unroll 4
        for (int k = 0; k < 64; k++) {
            float w = sW[k][t];
            unsigned long long wp = pack2(w, w);
            const unsigned long long* arow =
                (const unsigned long long*)&sInT[k0 + k][0];  // 136B rows: 8B-aligned
            #pragma unroll
            for (int j = 0; j < 16; j++)
                accp[j] = ffma2(arow[j], wp, accp[j]);
        }
    }
    float b = bias[t];
    #pragma unroll
    for (int j = 0; j < 16; j++) {
        float lo, hi;
        unpack2(accp[j], lo, hi);
        int n0 = nb + 2 * j;
        int n1 = n0 + 1;
        if (n0 < N_NODES) out[n0 * D + t] = lo + b;
        if (n1 < N_NODES) out[n1 * D + t] = hi + b;
    }
}

// ---------------- node encoder: h0 = relu(x@Wn1+bn1)@Wn2+bn2 -> g_hA ------------
__global__ void __launch_bounds__(128) node_encoder(
    const float* __restrict__ x,
    const float* __restrict__ Wn1, const float* __restrict__ bn1,
    const float* __restrict__ Wn2, const float* __restrict__ bn2)
{
    __shared__ float sInT[128][SIN_STRIDE];
    __shared__ float sW  [64][128];
    int nb = blockIdx.x * 32;
    int t  = threadIdx.x;

    float w[7];
    #pragma unroll
    for (int j = 0; j < 7; j++) w[j] = Wn1[j * D + t];
    float b1 = bn1[t];

    for (int n = 0; n < 32; n++) {
        int node = nb + n;
        float v = 0.f;
        if (node < N_NODES) {
            float s = b1;
            #pragma unroll
            for (int j = 0; j < 7; j++) s = fmaf(x[node * 7 + j], w[j], s);
            v = fmaxf(s, 0.f);
        }
        sInT[t][n] = v;
    }
    gemm128_tail_T(sInT, sW, Wn2, bn2, g_hA, nb, t);
}

// ---------------- gather + branchless online segment softmax --------------------
// Warp per dst node, 4 channels/lane. 2-stage pipeline + 2-exp rescale update
// (no divergent branches -> no BSSY/BSYNC chains).
__global__ void __launch_bounds__(256) genconv_gather(
    int hsel, const float* __restrict__ We, const float* __restrict__ be)
{
    const float* __restrict__ h = hsel ? g_hB : g_hA;
    int node = blockIdx.x * 8 + (threadIdx.x >> 5);
    if (node >= N_NODES) return;
    int lane = threadIdx.x & 31;
    int q    = lane << 2;

    int beg = g_row[node];
    int end = g_row[node + 1];

    float4 wv = *(const float4*)(We + q);
    float4 bv = *(const float4*)(be + q);

    float m0 = -1e30f, m1 = -1e30f, m2 = -1e30f, m3 = -1e30f;
    float d0 = 0.f, d1 = 0.f, d2 = 0.f, d3 = 0.f;
    float n0 = 0.f, n1 = 0.f, n2 = 0.f, n3 = 0.f;

    if (beg < end) {
        int2   epk = g_edge[beg];
        float4 hv  = *(const float4*)(h + epk.x * D + q);
        float  a   = __int_as_float(epk.y);

        for (int k = beg + 1; k < end; k++) {
            int2   epk_n = g_edge[k];
            float4 hv_n  = *(const float4*)(h + epk_n.x * D + q);
            float  a_n   = __int_as_float(epk_n.y);

            float msg0 = fmaxf(fmaf(a, wv.x, hv.x + bv.x), 0.f) + EPSF;
            float msg1 = fmaxf(fmaf(a, wv.y, hv.y + bv.y), 0.f) + EPSF;
            float msg2 = fmaxf(fmaf(a, wv.z, hv.z + bv.z), 0.f) + EPSF;
            float msg3 = fmaxf(fmaf(a, wv.w, hv.w + bv.w), 0.f) + EPSF;

            float mn, eo, en;
            mn = fmaxf(m0, msg0); eo = __expf(m0 - mn); en = __expf(msg0 - mn);
            d0 = fmaf(d0, eo, en); n0 = fmaf(n0, eo, en * msg0); m0 = mn;
            mn = fmaxf(m1, msg1); eo = __expf(m1 - mn); en = __expf(msg1 - mn);
            d1 = fmaf(d1, eo, en); n1 = fmaf(n1, eo, en * msg1); m1 = mn;
            mn = fmaxf(m2, msg2); eo = __expf(m2 - mn); en = __expf(msg2 - mn);
            d2 = fmaf(d2, eo, en); n2 = fmaf(n2, eo, en * msg2); m2 = mn;
            mn = fmaxf(m3, msg3); eo = __expf(m3 - mn); en = __expf(msg3 - mn);
            d3 = fmaf(d3, eo, en); n3 = fmaf(n3, eo, en * msg3); m3 = mn;

            hv = hv_n; a = a_n;
        }
        // drain last edge
        float msg0 = fmaxf(fmaf(a, wv.x, hv.x + bv.x), 0.f) + EPSF;
        float msg1 = fmaxf(fmaf(a, wv.y, hv.y + bv.y), 0.f) + EPSF;
        float msg2 = fmaxf(fmaf(a, wv.z, hv.z + bv.z), 0.f) + EPSF;
        float msg3 = fmaxf(fmaf(a, wv.w, hv.w + bv.w), 0.f) + EPSF;

        float mn, eo, en;
        mn = fmaxf(m0, msg0); eo = __expf(m0 - mn); en = __expf(msg0 - mn);
        d0 = fmaf(d0, eo, en); n0 = fmaf(n0, eo, en * msg0); m0 = mn;
        mn = fmaxf(m1, msg1); eo = __expf(m1 - mn); en = __expf(msg1 - mn);
        d1 = fmaf(d1, eo, en); n1 = fmaf(n1, eo, en * msg1); m1 = mn;
        mn = fmaxf(m2, msg2); eo = __expf(m2 - mn); en = __expf(msg2 - mn);
        d2 = fmaf(d2, eo, en); n2 = fmaf(n2, eo, en * msg2); m2 = mn;
        mn = fmaxf(m3, msg3); eo = __expf(m3 - mn); en = __expf(msg3 - mn);
        d3 = fmaf(d3, eo, en); n3 = fmaf(n3, eo, en * msg3); m3 = mn;
    }

    float4 hn = *(const float4*)(h + node * D + q);
    float4 o;
    o.x = (d0 > 0.f ? n0 / d0 : 0.f) + hn.x;
    o.y = (d1 > 0.f ? n1 / d1 : 0.f) + hn.y;
    o.z = (d2 > 0.f ? n2 / d2 : 0.f) + hn.z;
    o.w = (d3 > 0.f ? n3 / d3 : 0.f) + hn.w;
    *(float4*)(g_pre + node * D + q) = o;
}

// ---------------- node update: h_out = g_pre @ Wg + bg --------------------------
__global__ void __launch_bounds__(128) node_update(
    int hsel, const float* __restrict__ Wg_l, const float* __restrict__ bg_l)
{
    float* h_out = hsel ? g_hA : g_hB;

    __shared__ float sInT[128][SIN_STRIDE];
    __shared__ float sW  [64][128];
    int nb = blockIdx.x * 32;
    int t  = threadIdx.x;

    for (int n = 0; n < 32; n++) {
        int node = nb + n;
        sInT[t][n] = (node < N_NODES) ? g_pre[node * D + t] : 0.f;
    }
    gemm128_tail_T(sInT, sW, Wg_l, bg_l, h_out, nb, t);
}

// ---------------- output head: out = h @ Wo + bo  (warp per node) ---------------
__global__ void __launch_bounds__(256) head_kernel(
    const float* __restrict__ Wo, const float* __restrict__ bo,
    float* __restrict__ out)
{
    int warp = (blockIdx.x * 256 + threadIdx.x) >> 5;
    int lane = threadIdx.x & 31;
    if (warp >= N_NODES) return;
    const float* row = g_hA + warp * D;   // after 4 layers h lives in g_hA

    float a0 = 0.f, a1 = 0.f, a2 = 0.f;
    #pragma unroll
    for (int k = lane; k < D; k += 32) {
        float v = row[k];
        a0 = fmaf(v, Wo[k * 3 + 0], a0);
        a1 = fmaf(v, Wo[k * 3 + 1], a1);
        a2 = fmaf(v, Wo[k * 3 + 2], a2);
    }
    #pragma unroll
    for (int off = 16; off; off >>= 1) {
        a0 += __shfl_down_sync(0xffffffffu, a0, off);
        a1 += __shfl_down_sync(0xffffffffu, a1, off);
        a2 += __shfl_down_sync(0xffffffffu, a2, off);
    }
    if (lane == 0) {
        out[warp * 3 + 0] = a0 + bo[0];
        out[warp * 3 + 1] = a1 + bo[1];
        out[warp * 3 + 2] = a2 + bo[2];
    }
}

// ---------------- launch --------------------------------------------------------
extern "C" void kernel_launch(void* const* d_in, const int* in_sizes, int n_in,
                              void* d_out, int out_size)
{
    const float* x   = (const float*)d_in[0];
    const int*   ei  = (const int*)  d_in[1];
    const float* ea  = (const float*)d_in[2];
    const float* Wn1 = (const float*)d_in[3];
    const float* bn1 = (const float*)d_in[4];
    const float* Wn2 = (const float*)d_in[5];
    const float* bn2 = (const float*)d_in[6];
    const float* We  = (const float*)d_in[7];
    const float* be  = (const float*)d_in[8];
    const float* Wg  = (const float*)d_in[9];
    const float* bg  = (const float*)d_in[10];
    const float* Wo  = (const float*)d_in[11];
    const float* bo  = (const float*)d_in[12];
    float* out = (float*)d_out;

    const int NODE_BLOCKS   = (N_NODES + 31) / 32;        // 938
    const int EDGE_BLOCKS   = (N_EDGES + 255) / 256;      // 1875
    const int CNT_BLOCKS    = (N_NODES + 255) / 256;      // 118
    const int GATHER_BLOCKS = (N_NODES + 7) / 8;          // 3750 (8 warps/block)

    // CSR build (graph constant; recomputed every call for determinism)
    csr_zero   <<<CNT_BLOCKS, 256>>>();
    csr_hist   <<<EDGE_BLOCKS, 256>>>(ei);
    csr_scan   <<<1, 1024>>>();
    csr_scatter<<<EDGE_BLOCKS, 256>>>(ei, ea);

    node_encoder<<<NODE_BLOCKS, 128>>>(x, Wn1, bn1, Wn2, bn2);

    for (int l = 0; l < 4; l++) {
        int hsel = l & 1;   // 0: h in g_hA, 1: h in g_hB
        genconv_gather<<<GATHER_BLOCKS, 256>>>(hsel, We, be);
        node_update   <<<NODE_BLOCKS, 128>>>(hsel, Wg + (size_t)l * D * D, bg + (size_t)l * D);
    }

    head_kernel<<<(N_NODES * 32 + 255) / 256, 256>>>(Wo, bo, out);
}